// round 15
// baseline (speedup 1.0000x reference)
#include <cuda_runtime.h>

// ---------------------------------------------------------------------------
// SpMiddleFHD. Sparsity: 0.355% occupancy => ~3.7K non-self neighbor pairs.
// Submanifold convs = dense self-term GEMV + sparse pair corrections into
// SEPARATE zero-invariant correction buffers (x1c/x2c), letting independent
// stages fuse into single launches as disjoint block ranges:
//   K1 scatter  K2 probe||dense1  K3 pairs1->x1c  K4 dense2||pairs2->x2c
//   K5 conv3 (atomics into g_acc, clears x1c)  K6 finalize (writes out once,
//   self-cleans acc/flags, clears x2c).
// 6 launches (launch+wave overhead ~4us each was ~30us of the R12 total).
// All scratch invariants restored every call (graph-replay safe).
// ---------------------------------------------------------------------------

namespace {
constexpr int kB  = 2;
constexpr int kDZ = 41, kHY = 400, kWX = 352;
constexpr int kGD = kDZ + 2, kGH = kHY + 2, kGW = kWX + 2;
constexpr int kN  = 40000;
constexpr int kDO = 21, kHO = 200, kWO = 176;
constexpr int kGridCells = kB * kGD * kGH * kGW;      // 12,238,488
constexpr int kBitWords  = (kGridCells + 31) / 32;    // ~1.53MB bitmap
constexpr int kMaxPairs  = kN * 27;
constexpr int kVox       = kB * kDO * kHO * kWO;      // 1,478,400 voxels

constexpr int kD1Blocks = (kN / 16 + 7) / 8;          // 313 dense1 blocks
constexpr int kPrBlocks = 1016;                       // probe blocks
constexpr int kD2Blocks = (kN * 16 + 255) / 256;      // 2500 dense2 blocks
constexpr int kP2Blocks = 512;                        // pairs2 blocks
}

__device__ unsigned short g_grid[kGridCells];         // idx+1 (0 empty)
__device__ unsigned int   g_bit[kBitWords];           // occupancy bitmap
__device__ int  g_np;                                 // pair counter
__device__ int2 g_pairs[kMaxPairs];                   // {n, (k<<16)|idx}
__device__ __align__(16) float g_x1 [kN * 16];        // dense conv1 (pre-relu)
__device__ __align__(16) float g_x1c[kN * 16];        // conv1 corrections
__device__ __align__(16) float g_x2 [kN * 16];        // dense conv2 (pre-relu)
__device__ __align__(16) float g_x2c[kN * 16];        // conv2 corrections
__device__ __align__(16) float g_acc[(size_t)kVox * 32];  // 189MB accumulator
__device__ unsigned char g_flag[kVox];                // touch flags

__device__ __forceinline__ int cell_of(int4 c) {
    return ((c.x * kGD + c.y + 1) * kGH + c.z + 1) * kGW + c.w + 1;
}

// --------------------------------------------------------------------- K1 --
__global__ void k_scatter(const int4* __restrict__ coors) {
    int n = blockIdx.x * blockDim.x + threadIdx.x;
    if (n == 0) g_np = 0;
    if (n >= kN) return;
    int4 c = __ldg(&coors[n]);
    int cell = cell_of(c);
    g_grid[cell] = (unsigned short)(n + 1);
    atomicOr(&g_bit[cell >> 5], 1u << (cell & 31));
}

// --------------------------------------------------------------------- K2 --
// blockIdx.x < kD1Blocks: dense conv1 (W1[13] in regs, 16 points/warp).
// else: bitmap-gated pair probe (grid-stride over kN*13 probes).
__global__ void __launch_bounds__(256)
k_probe_dense1(const float4* __restrict__ fv,
               const float4* __restrict__ w1v,
               const int4* __restrict__ coors) {
    if (blockIdx.x < kD1Blocks) {
        int w    = blockIdx.x * 8 + (threadIdx.x >> 5);
        int lane = threadIdx.x & 31;
        int n0   = w * 16;
        if (n0 >= kN) return;
        int dq = lane & 3, cg = lane >> 2;

        float4 wv[16];
        const float4* wb = &w1v[13 * 512 + dq];
        #pragma unroll
        for (int e = 0; e < 16; e++) wv[e] = __ldg(&wb[(cg * 16 + e) * 4]);

        #pragma unroll
        for (int rep = 0; rep < 4; rep++) {
            int nb = n0 + rep * 4;
            float4 acc[4];
            #pragma unroll
            for (int p = 0; p < 4; p++) {
                float fs[16];
                #pragma unroll
                for (int q = 0; q < 4; q++) {
                    float4 f = __ldcg(&fv[(nb + p) * 32 + cg * 4 + q]);
                    fs[q*4+0] = f.x; fs[q*4+1] = f.y;
                    fs[q*4+2] = f.z; fs[q*4+3] = f.w;
                }
                float4 a = make_float4(0.f, 0.f, 0.f, 0.f);
                #pragma unroll
                for (int e = 0; e < 16; e++) {
                    float f = fs[e];
                    a.x += f * wv[e].x; a.y += f * wv[e].y;
                    a.z += f * wv[e].z; a.w += f * wv[e].w;
                }
                acc[p] = a;
            }
            #pragma unroll
            for (int p = 0; p < 4; p++) {
                #pragma unroll
                for (int o = 4; o < 32; o <<= 1) {
                    acc[p].x += __shfl_xor_sync(0xffffffffu, acc[p].x, o);
                    acc[p].y += __shfl_xor_sync(0xffffffffu, acc[p].y, o);
                    acc[p].z += __shfl_xor_sync(0xffffffffu, acc[p].z, o);
                    acc[p].w += __shfl_xor_sync(0xffffffffu, acc[p].w, o);
                }
                if (cg == 0)
                    reinterpret_cast<float4*>(g_x1)[(nb + p) * 4 + dq] = acc[p];
            }
        }
    } else {
        int stride = kPrBlocks * 256;
        for (int t = (blockIdx.x - kD1Blocks) * 256 + threadIdx.x;
             t < kN * 13; t += stride) {
            int n = t / 13, j = t - n * 13;
            int4 c = __ldg(&coors[n]);
            int dk = j / 9, dy = (j / 3) % 3, dx = j % 3;
            int cell = ((c.x * kGD + c.y + dk) * kGH + c.z + dy) * kGW
                       + c.w + dx;
            if (!((g_bit[cell >> 5] >> (cell & 31)) & 1u)) continue;
            int m = (int)g_grid[cell] - 1;
            if (m >= 0) {
                int base = atomicAdd(&g_np, 2);
                g_pairs[base]     = make_int2(n, (j << 16) | m);
                g_pairs[base + 1] = make_int2(m, ((26 - j) << 16) | n);
            }
        }
    }
}

// --------------------------------------------------------------------- K3 --
// Sparse conv1 corrections into g_x1c: warp per pair, grid-stride.
__global__ void k_pairs1(const float4* __restrict__ fv,
                         const float4* __restrict__ w1v) {
    int wflat  = blockIdx.x * (blockDim.x >> 5) + (threadIdx.x >> 5);
    int nwarps = gridDim.x * (blockDim.x >> 5);
    int lane   = threadIdx.x & 31;
    int dq = lane & 3, cg = lane >> 2;
    int np = g_np;

    for (int p = wflat; p < np; p += nwarps) {
        int2 pr = g_pairs[p];
        int n = pr.x, k = pr.y >> 16, idx = pr.y & 0xffff;

        float fs[16];
        #pragma unroll
        for (int q = 0; q < 4; q++) {
            float4 f = __ldcg(&fv[idx * 32 + cg * 4 + q]);
            fs[q*4+0] = f.x; fs[q*4+1] = f.y; fs[q*4+2] = f.z; fs[q*4+3] = f.w;
        }

        float4 acc = make_float4(0.f, 0.f, 0.f, 0.f);
        const float4* wb = &w1v[k * 512 + dq];
        #pragma unroll
        for (int e = 0; e < 16; e++) {
            float4 wv = __ldg(&wb[(cg * 16 + e) * 4]);
            float f = fs[e];
            acc.x += f * wv.x; acc.y += f * wv.y;
            acc.z += f * wv.z; acc.w += f * wv.w;
        }
        #pragma unroll
        for (int o = 4; o < 32; o <<= 1) {
            acc.x += __shfl_xor_sync(0xffffffffu, acc.x, o);
            acc.y += __shfl_xor_sync(0xffffffffu, acc.y, o);
            acc.z += __shfl_xor_sync(0xffffffffu, acc.z, o);
            acc.w += __shfl_xor_sync(0xffffffffu, acc.w, o);
        }
        if (cg == 0) {
            float* dst = &g_x1c[n * 16 + dq * 4];
            atomicAdd(dst + 0, acc.x); atomicAdd(dst + 1, acc.y);
            atomicAdd(dst + 2, acc.z); atomicAdd(dst + 3, acc.w);
        }
    }
}

// --------------------------------------------------------------------- K4 --
// blockIdx.x < kD2Blocks: dense conv2 -> g_x2 (reads relu(x1+x1c); clears
// grid/bitmap). else: sparse conv2 corrections -> g_x2c (half-warp per pair).
__global__ void k_conv2(const float* __restrict__ W2,
                        const int4* __restrict__ coors) {
    if (blockIdx.x < kD2Blocks) {
        int t = blockIdx.x * blockDim.x + threadIdx.x;
        int n = t >> 4, d = t & 15;
        if (n >= kN) return;

        const float* xr = &g_x1[n * 16];
        const float* xc = &g_x1c[n * 16];
        const float* wr = &W2[13 * 256 + d];
        float acc = 0.f;
        #pragma unroll
        for (int cc = 0; cc < 16; cc++)
            acc += fmaxf(xr[cc] + xc[cc], 0.f) * __ldg(&wr[cc * 16]);
        g_x2[n * 16 + d] = acc;

        if (d == 0) {
            int4 c = __ldg(&coors[n]);
            int cell = cell_of(c);
            g_grid[cell] = 0;
            atomicAnd(&g_bit[cell >> 5], ~(1u << (cell & 31)));
        }
    } else {
        int hw  = ((blockIdx.x - kD2Blocks) * blockDim.x + threadIdx.x) >> 4;
        int nhw = (kP2Blocks * blockDim.x) >> 4;
        int d   = threadIdx.x & 15;
        int np  = g_np;

        for (int p = hw; p < np; p += nhw) {
            int2 pr = g_pairs[p];
            int n = pr.x, k = pr.y >> 16, idx = pr.y & 0xffff;
            const float* xr = &g_x1[idx * 16];
            const float* xc = &g_x1c[idx * 16];
            const float* wr = &W2[k * 256 + d];
            float acc = 0.f;
            #pragma unroll
            for (int cc = 0; cc < 16; cc++)
                acc += fmaxf(xr[cc] + xc[cc], 0.f) * __ldg(&wr[cc * 16]);
            atomicAdd(&g_x2c[n * 16 + d], acc);
        }
    }
}

// --------------------------------------------------------------------- K5 --
// conv3 (16->32) + strided scatter into g_acc; x = relu(x2+x2c).
// Warp per (n, dk). Also clears x1c (never read here; idempotent).
__global__ void k_conv3_acc(const int4* __restrict__ coors,
                            const float* __restrict__ W3) {
    int n    = blockIdx.x * (blockDim.x >> 5) + (threadIdx.x >> 5);
    int lane = threadIdx.x & 31;
    int dk   = blockIdx.y;
    if (n >= kN) return;

    if (dk == 0 && lane < 16) g_x1c[n * 16 + lane] = 0.f;  // restore invariant

    int4 c = __ldg(&coors[n]);
    int oz = c.y + 1 - dk;
    if (oz < 0 || (oz & 1)) return;
    int pz = oz >> 1;
    if (pz >= kDO) return;

    const float4* x2v  = reinterpret_cast<const float4*>(&g_x2[n * 16]);
    const float4* x2cv = reinterpret_cast<const float4*>(&g_x2c[n * 16]);
    float xs[16];
    #pragma unroll
    for (int q = 0; q < 4; q++) {
        float4 v = x2v[q], u = x2cv[q];
        xs[q*4+0] = fmaxf(v.x + u.x, 0.f); xs[q*4+1] = fmaxf(v.y + u.y, 0.f);
        xs[q*4+2] = fmaxf(v.z + u.z, 0.f); xs[q*4+3] = fmaxf(v.w + u.w, 0.f);
    }

    for (int dy = 0; dy < 3; dy++) {
        int oy = c.z + 1 - dy;
        if (oy < 0 || (oy & 1)) continue;
        int py = oy >> 1;
        if (py >= kHO) continue;
        for (int dx = 0; dx < 3; dx++) {
            int ox = c.w + 1 - dx;
            if (ox < 0 || (ox & 1)) continue;
            int px = ox >> 1;
            if (px >= kWO) continue;
            int k    = dk * 9 + dy * 3 + dx;
            int base = ((c.x * kDO + pz) * kHO + py) * kWO + px;
            float v = 0.f;
            #pragma unroll
            for (int cc = 0; cc < 16; cc++)
                v += xs[cc] * __ldg(&W3[(k * 16 + cc) * 32 + lane]);
            atomicAdd(&g_acc[(size_t)base * 32 + lane], v);
            if (lane == 0) g_flag[base] = 1;      // racing 1-stores, benign
        }
    }
}

// --------------------------------------------------------------------- K6 --
// Single streaming write of the whole output; self-cleans acc + flags.
// Two float4s per thread (ILP). First kN*4 threads also clear x2c
// (never read in this kernel).
__global__ void k_finalize(float4* __restrict__ out, int n4, int half4) {
    int i0 = blockIdx.x * blockDim.x + threadIdx.x;
    float4 z = make_float4(0.f, 0.f, 0.f, 0.f);
    float4* av = reinterpret_cast<float4*>(g_acc);

    if (i0 < kN * 4) reinterpret_cast<float4*>(g_x2c)[i0] = z;

    #pragma unroll
    for (int r = 0; r < 2; r++) {
        int i = i0 + r * half4;
        if (i >= n4) continue;
        int v = i >> 3;
        if (g_flag[v]) {
            float4 a = av[i];
            out[i] = make_float4(fmaxf(a.x, 0.f), fmaxf(a.y, 0.f),
                                 fmaxf(a.z, 0.f), fmaxf(a.w, 0.f));
            av[i] = z;                            // restore invariant
            if ((i & 7) == 0) g_flag[v] = 0;
        } else {
            out[i] = z;
        }
    }
}

// ---------------------------------------------------------------------------
extern "C" void kernel_launch(void* const* d_in, const int* in_sizes, int n_in,
                              void* d_out, int out_size) {
    const float* feat  = (const float*)d_in[0];
    const int4*  coors = (const int4*) d_in[1];
    const float* W1    = (const float*)d_in[2];
    const float* W2    = (const float*)d_in[3];
    const float* W3    = (const float*)d_in[4];
    float*       out   = (float*)d_out;
    (void)in_sizes; (void)n_in;

    int n4    = out_size / 4;                     // 11,827,200 float4s
    int half4 = (n4 + 1) / 2;
    dim3 g3((kN + 7) / 8, 3);

    k_scatter      <<<(kN + 255) / 256, 256>>>(coors);
    k_probe_dense1 <<<kD1Blocks + kPrBlocks, 256>>>((const float4*)feat,
                                                    (const float4*)W1, coors);
    k_pairs1       <<<1024, 256>>>((const float4*)feat, (const float4*)W1);
    k_conv2        <<<kD2Blocks + kP2Blocks, 256>>>(W2, coors);
    k_conv3_acc    <<<g3, 256>>>(coors, W3);
    k_finalize     <<<(half4 + 255) / 256, 256>>>((float4*)out, n4, half4);
}

// round 16
// speedup vs baseline: 1.4229x; 1.4229x over previous
#include <cuda_runtime.h>

// ---------------------------------------------------------------------------
// SpMiddleFHD. Sparsity: 0.355% occupancy => ~3.7K non-self neighbor pairs.
// Submanifold convs = dense self-term GEMV + tiny sparse pair corrections.
// Pair probing is gated by a 1.5MB L2-resident occupancy bitmap; the 24.5MB
// uint16 grid is read only on hits. conv3 scatters atomically into the
// zero-invariant accumulator g_acc + per-voxel flags; one streaming finalize
// writes the output exactly once (flag ? relu(acc) : 0) with evict-first
// cache policy and self-cleans acc/flags. Single stream throughout.
// All scratch invariants restored every call (graph-replay safe).
// ---------------------------------------------------------------------------

namespace {
constexpr int kB  = 2;
constexpr int kDZ = 41, kHY = 400, kWX = 352;
constexpr int kGD = kDZ + 2, kGH = kHY + 2, kGW = kWX + 2;
constexpr int kN  = 40000;
constexpr int kDO = 21, kHO = 200, kWO = 176;
constexpr int kGridCells = kB * kGD * kGH * kGW;      // 12,238,488
constexpr int kBitWords  = (kGridCells + 31) / 32;    // ~1.53MB bitmap
constexpr int kMaxPairs  = kN * 27;
constexpr int kVox       = kB * kDO * kHO * kWO;      // 1,478,400 voxels
}

__device__ unsigned short g_grid[kGridCells];         // idx+1 (0 empty)
__device__ unsigned int   g_bit[kBitWords];           // occupancy bitmap
__device__ int  g_np;                                 // pair counter
__device__ int2 g_pairs[kMaxPairs];                   // {n, (k<<16)|idx}
__device__ __align__(16) float g_x1[kN * 16];         // pre-relu conv1 out
__device__ __align__(16) float g_x2[kN * 16];         // pre-relu conv2 out
__device__ __align__(16) float g_acc[(size_t)kVox * 32];  // 189MB accumulator
__device__ unsigned char g_flag[kVox];                // touch flags

__device__ __forceinline__ int cell_of(int4 c) {
    return ((c.x * kGD + c.y + 1) * kGH + c.z + 1) * kGW + c.w + 1;
}

// ---------------------------------------------------------------------------
__global__ void k_scatter(const int4* __restrict__ coors) {
    int n = blockIdx.x * blockDim.x + threadIdx.x;
    if (n == 0) g_np = 0;
    if (n >= kN) return;
    int4 c = __ldg(&coors[n]);
    int cell = cell_of(c);
    g_grid[cell] = (unsigned short)(n + 1);
    atomicOr(&g_bit[cell >> 5], 1u << (cell & 31));
}

// Thread per (point, offset<13). Bitmap gate (L2-resident); uint16 grid read
// on hit only. Each hit (n,m,j) also emits (m,n,26-j): every directed
// non-self pair appears exactly once.
__global__ void k_pairs_probe(const int4* __restrict__ coors) {
    int t = blockIdx.x * blockDim.x + threadIdx.x;
    if (t >= kN * 13) return;
    int n = t / 13, j = t - n * 13;
    int4 c = __ldg(&coors[n]);
    int dk = j / 9, dy = (j / 3) % 3, dx = j % 3;
    int cell = ((c.x * kGD + c.y + dk) * kGH + c.z + dy) * kGW + c.w + dx;
    if (!((g_bit[cell >> 5] >> (cell & 31)) & 1u)) return;
    int m = (int)g_grid[cell] - 1;
    if (m >= 0) {
        int base = atomicAdd(&g_np, 2);
        g_pairs[base]     = make_int2(n, (j << 16) | m);
        g_pairs[base + 1] = make_int2(m, ((26 - j) << 16) | n);
    }
}

// ---------------------------------------------------------------------------
// Dense conv1 self-term: x1[n] = feat[n] . W1[13] (pre-relu store).
// W1[13] hoisted into registers, reused for 16 points/warp.
__global__ void __launch_bounds__(256) k_dense1(const float4* __restrict__ fv,
                                                const float4* __restrict__ w1v) {
    int w    = blockIdx.x * (blockDim.x >> 5) + (threadIdx.x >> 5);
    int lane = threadIdx.x & 31;
    int n0   = w * 16;
    if (n0 >= kN) return;
    int dq = lane & 3, cg = lane >> 2;

    float4 wv[16];
    const float4* wb = &w1v[13 * 512 + dq];
    #pragma unroll
    for (int e = 0; e < 16; e++) wv[e] = __ldg(&wb[(cg * 16 + e) * 4]);

    #pragma unroll
    for (int rep = 0; rep < 4; rep++) {
        int nb = n0 + rep * 4;
        float4 acc[4];
        #pragma unroll
        for (int p = 0; p < 4; p++) {
            float fs[16];
            #pragma unroll
            for (int q = 0; q < 4; q++) {
                float4 f = __ldcg(&fv[(nb + p) * 32 + cg * 4 + q]);
                fs[q*4+0] = f.x; fs[q*4+1] = f.y;
                fs[q*4+2] = f.z; fs[q*4+3] = f.w;
            }
            float4 a = make_float4(0.f, 0.f, 0.f, 0.f);
            #pragma unroll
            for (int e = 0; e < 16; e++) {
                float f = fs[e];
                a.x += f * wv[e].x; a.y += f * wv[e].y;
                a.z += f * wv[e].z; a.w += f * wv[e].w;
            }
            acc[p] = a;
        }
        #pragma unroll
        for (int p = 0; p < 4; p++) {
            #pragma unroll
            for (int o = 4; o < 32; o <<= 1) {
                acc[p].x += __shfl_xor_sync(0xffffffffu, acc[p].x, o);
                acc[p].y += __shfl_xor_sync(0xffffffffu, acc[p].y, o);
                acc[p].z += __shfl_xor_sync(0xffffffffu, acc[p].z, o);
                acc[p].w += __shfl_xor_sync(0xffffffffu, acc[p].w, o);
            }
            if (cg == 0)
                reinterpret_cast<float4*>(g_x1)[(nb + p) * 4 + dq] = acc[p];
        }
    }
}

// Sparse conv1 corrections: warp per pair, grid-stride.
__global__ void k_pairs1(const float4* __restrict__ fv,
                         const float4* __restrict__ w1v) {
    int wflat  = blockIdx.x * (blockDim.x >> 5) + (threadIdx.x >> 5);
    int nwarps = gridDim.x * (blockDim.x >> 5);
    int lane   = threadIdx.x & 31;
    int dq = lane & 3, cg = lane >> 2;
    int np = g_np;

    for (int p = wflat; p < np; p += nwarps) {
        int2 pr = g_pairs[p];
        int n = pr.x, k = pr.y >> 16, idx = pr.y & 0xffff;

        float fs[16];
        #pragma unroll
        for (int q = 0; q < 4; q++) {
            float4 f = __ldcg(&fv[idx * 32 + cg * 4 + q]);
            fs[q*4+0] = f.x; fs[q*4+1] = f.y; fs[q*4+2] = f.z; fs[q*4+3] = f.w;
        }

        float4 acc = make_float4(0.f, 0.f, 0.f, 0.f);
        const float4* wb = &w1v[k * 512 + dq];
        #pragma unroll
        for (int e = 0; e < 16; e++) {
            float4 wv = __ldg(&wb[(cg * 16 + e) * 4]);
            float f = fs[e];
            acc.x += f * wv.x; acc.y += f * wv.y;
            acc.z += f * wv.z; acc.w += f * wv.w;
        }
        #pragma unroll
        for (int o = 4; o < 32; o <<= 1) {
            acc.x += __shfl_xor_sync(0xffffffffu, acc.x, o);
            acc.y += __shfl_xor_sync(0xffffffffu, acc.y, o);
            acc.z += __shfl_xor_sync(0xffffffffu, acc.z, o);
            acc.w += __shfl_xor_sync(0xffffffffu, acc.w, o);
        }
        if (cg == 0) {
            float* dst = &g_x1[n * 16 + dq * 4];
            atomicAdd(dst + 0, acc.x); atomicAdd(dst + 1, acc.y);
            atomicAdd(dst + 2, acc.z); atomicAdd(dst + 3, acc.w);
        }
    }
}

// ---------------------------------------------------------------------------
// Dense conv2 self-term; clears this point's grid cell + bitmap bit.
__global__ void k_dense2(const float* __restrict__ W2,
                         const int4* __restrict__ coors) {
    int t = blockIdx.x * blockDim.x + threadIdx.x;
    int n = t >> 4, d = t & 15;
    if (n >= kN) return;

    const float* xr = &g_x1[n * 16];
    const float* wr = &W2[13 * 256 + d];
    float acc = 0.f;
    #pragma unroll
    for (int cc = 0; cc < 16; cc++)
        acc += fmaxf(xr[cc], 0.f) * __ldg(&wr[cc * 16]);
    g_x2[n * 16 + d] = acc;

    if (d == 0) {
        int4 c = __ldg(&coors[n]);
        int cell = cell_of(c);
        g_grid[cell] = 0;
        atomicAnd(&g_bit[cell >> 5], ~(1u << (cell & 31)));
    }
}

// Sparse conv2 corrections: half-warp per pair, grid-stride.
__global__ void k_pairs2(const float* __restrict__ W2) {
    int hw  = (blockIdx.x * blockDim.x + threadIdx.x) >> 4;
    int nhw = (gridDim.x * blockDim.x) >> 4;
    int d   = threadIdx.x & 15;
    int np  = g_np;

    for (int p = hw; p < np; p += nhw) {
        int2 pr = g_pairs[p];
        int n = pr.x, k = pr.y >> 16, idx = pr.y & 0xffff;
        const float* xr = &g_x1[idx * 16];
        const float* wr = &W2[k * 256 + d];
        float acc = 0.f;
        #pragma unroll
        for (int cc = 0; cc < 16; cc++)
            acc += fmaxf(xr[cc], 0.f) * __ldg(&wr[cc * 16]);
        atomicAdd(&g_x2[n * 16 + d], acc);
    }
}

// ---------------------------------------------------------------------------
// conv3 (16->32) + strided scatter into g_acc; sets per-voxel touch flag.
// Warp per (n, dk); lane = output channel.
__global__ void k_conv3_acc(const int4* __restrict__ coors,
                            const float* __restrict__ W3) {
    int n    = blockIdx.x * (blockDim.x >> 5) + (threadIdx.x >> 5);
    int lane = threadIdx.x & 31;
    int dk   = blockIdx.y;
    if (n >= kN) return;

    int4 c = __ldg(&coors[n]);
    int oz = c.y + 1 - dk;
    if (oz < 0 || (oz & 1)) return;
    int pz = oz >> 1;
    if (pz >= kDO) return;

    const float4* x2v = reinterpret_cast<const float4*>(&g_x2[n * 16]);
    float xs[16];
    #pragma unroll
    for (int q = 0; q < 4; q++) {
        float4 v = x2v[q];
        xs[q*4+0] = fmaxf(v.x, 0.f); xs[q*4+1] = fmaxf(v.y, 0.f);
        xs[q*4+2] = fmaxf(v.z, 0.f); xs[q*4+3] = fmaxf(v.w, 0.f);
    }

    for (int dy = 0; dy < 3; dy++) {
        int oy = c.z + 1 - dy;
        if (oy < 0 || (oy & 1)) continue;
        int py = oy >> 1;
        if (py >= kHO) continue;
        for (int dx = 0; dx < 3; dx++) {
            int ox = c.w + 1 - dx;
            if (ox < 0 || (ox & 1)) continue;
            int px = ox >> 1;
            if (px >= kWO) continue;
            int k    = dk * 9 + dy * 3 + dx;
            int base = ((c.x * kDO + pz) * kHO + py) * kWO + px;
            float v = 0.f;
            #pragma unroll
            for (int cc = 0; cc < 16; cc++)
                v += xs[cc] * __ldg(&W3[(k * 16 + cc) * 32 + lane]);
            atomicAdd(&g_acc[(size_t)base * 32 + lane], v);
            if (lane == 0) g_flag[base] = 1;      // racing 1-stores, benign
        }
    }
}

// Single streaming write of the whole output; self-cleans acc + flags.
// 4 independent float4 chunks per thread (store MLP); out/acc use
// evict-first (.cs) policy since neither is re-read this launch.
__global__ void k_finalize(float4* __restrict__ out, int n4, int q4) {
    int i0 = blockIdx.x * blockDim.x + threadIdx.x;
    float4 z = make_float4(0.f, 0.f, 0.f, 0.f);
    float4* av = reinterpret_cast<float4*>(g_acc);
    #pragma unroll
    for (int r = 0; r < 4; r++) {
        int i = i0 + r * q4;
        if (i >= n4) continue;
        int v = i >> 3;
        if (g_flag[v]) {
            float4 a = __ldcs(&av[i]);
            __stcs(&out[i], make_float4(fmaxf(a.x, 0.f), fmaxf(a.y, 0.f),
                                        fmaxf(a.z, 0.f), fmaxf(a.w, 0.f)));
            __stcs(&av[i], z);                    // restore invariant
            if ((i & 7) == 0) g_flag[v] = 0;
        } else {
            __stcs(&out[i], z);
        }
    }
}

// ---------------------------------------------------------------------------
extern "C" void kernel_launch(void* const* d_in, const int* in_sizes, int n_in,
                              void* d_out, int out_size) {
    const float* feat  = (const float*)d_in[0];
    const int4*  coors = (const int4*) d_in[1];
    const float* W1    = (const float*)d_in[2];
    const float* W2    = (const float*)d_in[3];
    const float* W3    = (const float*)d_in[4];
    float*       out   = (float*)d_out;
    (void)in_sizes; (void)n_in;

    int n4 = out_size / 4;                        // 11,827,200 float4s
    int q4 = (n4 + 3) / 4;
    dim3 g3((kN + 7) / 8, 3);

    k_scatter     <<<(kN + 255) / 256, 256>>>(coors);
    k_pairs_probe <<<(kN * 13 + 255) / 256, 256>>>(coors);
    k_dense1      <<<(kN / 16 + 7) / 8, 256>>>((const float4*)feat,
                                               (const float4*)W1);
    k_pairs1      <<<1024, 256>>>((const float4*)feat, (const float4*)W1);
    k_dense2      <<<(kN * 16 + 255) / 256, 256>>>(W2, coors);
    k_pairs2      <<<512, 256>>>(W2);
    k_conv3_acc   <<<g3, 256>>>(coors, W3);
    k_finalize    <<<(q4 + 255) / 256, 256>>>((float4*)out, n4, q4);
}